// round 6
// baseline (speedup 1.0000x reference)
#include <cuda_runtime.h>
#include <cuda_bf16.h>

#define B_  256
#define S_  256
#define E_  256
#define H_  1024
#define G4  4096

typedef unsigned int u32;
typedef unsigned long long u64;

// ---------------- device globals (static, no runtime alloc) ----------------
__device__ float g_projL[30 * G4];
__device__ float g_projS[4 * G4];
__device__ __nv_bfloat16 g_Whi[(size_t)G4 * H_];   // [c][kk], c = 4k+g reordered
__device__ __nv_bfloat16 g_Wlo[(size_t)G4 * H_];
__device__ __nv_bfloat16 g_hhi[2][B_ * H_];        // [parity][b*H+k]
__device__ __nv_bfloat16 g_hlo[2][B_ * H_];
__device__ u32 g_bars[64];                         // per-bt barrier (padded)

// ---------------- SMEM layout ----------------
// [8..40)   : mbarriers full0,full1,empty0,empty1
// [1024..)  : resident Whi, 16 chunks x 8192B (SW128 per chunk)
// SM_STAGE  : 2 staging buffers (Ahi 16K | Alo 16K | Blo 8K each)
#define SM_FULL0   8
#define SM_FULL1   16
#define SM_EMPTY0  24
#define SM_EMPTY1  32
#define SM_WHI     1024
#define SM_STAGE   132096          // 1024 + 16*8192
#define STAGE_SZ   40960
#define OFF_AHI    0
#define OFF_ALO    16384
#define OFF_BLO    32768
#define EPI_STRIDE 80              // bytes per row in per-warp epilogue slab
#define EPI_SLAB   5120            // 64 rows * 80B
#define SMEM_TOTAL 214016

#define SWZ(x) ((x) ^ (((x) >> 3) & 0x70))

static __device__ __forceinline__ u32 smem_u32(const void* p) {
    u32 a;
    asm("{ .reg .u64 t; cvta.to.shared.u64 t, %1; cvt.u32.u64 %0, t; }"
        : "=r"(a) : "l"(p));
    return a;
}
#define CP16(dst, src) asm volatile( \
    "cp.async.cg.shared.global [%0], [%1], 16;" :: "r"(dst), "l"(src) : "memory")
#define CP_COMMIT() asm volatile("cp.async.commit_group;" ::: "memory")
#define CP_WAIT0()  asm volatile("cp.async.wait_group 0;" ::: "memory")
#define CP_WAIT1()  asm volatile("cp.async.wait_group 1;" ::: "memory")

#define MBINIT(a, c) asm volatile("mbarrier.init.shared.b64 [%0], %1;" \
    :: "r"(a), "r"((u32)(c)) : "memory")
#define MBARRIVE(a) asm volatile("mbarrier.arrive.shared.b64 _, [%0];" \
    :: "r"(a) : "memory")
#define MBWAIT(addr, par) do {                                                   \
    u32 _a = (addr); u32 _p = (u32)(par); u32 _d;                                \
    asm volatile("{\n\t.reg .pred P;\n\t"                                        \
        "mbarrier.try_wait.parity.acquire.cta.shared::cta.b64 P, [%1], %2;\n\t"  \
        "selp.b32 %0, 1, 0, P;\n\t}"                                             \
        : "=r"(_d) : "r"(_a), "r"(_p) : "memory");                               \
    if (!_d) {                                                                   \
        asm volatile("{\n\t.reg .pred P;\n\t"                                    \
            "WL_%=:\n\t"                                                         \
            "mbarrier.try_wait.parity.acquire.cta.shared::cta.b64 P, [%0], %1, 0x989680;\n\t" \
            "@P bra WD_%=;\n\t"                                                  \
            "bra WL_%=;\n\t"                                                     \
            "WD_%=:\n\t}"                                                        \
            :: "r"(_a), "r"(_p) : "memory");                                     \
    } } while (0)

#define LDSM_X4(r, addr) asm volatile( \
    "ldmatrix.sync.aligned.m8n8.x4.shared.b16 {%0,%1,%2,%3}, [%4];" \
    : "=r"((r)[0]), "=r"((r)[1]), "=r"((r)[2]), "=r"((r)[3]) : "r"(addr))

#define MMA16816(d, a, b) asm volatile( \
    "mma.sync.aligned.m16n8k16.row.col.f32.bf16.bf16.f32 " \
    "{%0,%1,%2,%3}, {%4,%5,%6,%7}, {%8,%9}, {%0,%1,%2,%3};" \
    : "+f"((d)[0]), "+f"((d)[1]), "+f"((d)[2]), "+f"((d)[3]) \
    : "r"((a)[0]), "r"((a)[1]), "r"((a)[2]), "r"((a)[3]), \
      "r"((b)[0]), "r"((b)[1]))

#define LDS128F(v, addr) asm volatile("ld.shared.v4.f32 {%0,%1,%2,%3}, [%4];" \
    : "=f"((v).x), "=f"((v).y), "=f"((v).z), "=f"((v).w) : "r"(addr))
#define STS64F(addr, x, y) asm volatile("st.shared.v2.f32 [%0], {%1,%2};" \
    :: "r"(addr), "f"(x), "f"(y) : "memory")

static __device__ __forceinline__ float sigf(float x) {
    return __fdividef(1.0f, 1.0f + __expf(-x));
}
static __device__ __forceinline__ float tanhfast(float x) {
    return __fdividef(2.0f, 1.0f + __expf(-2.0f * x)) - 1.0f;
}

// ---------------- prep kernels ----------------
__global__ void zero_kernel() {
    int idx = blockIdx.x * blockDim.x + threadIdx.x;
    if (idx < B_ * H_) {
        g_hhi[0][idx] = __float2bfloat16(0.0f);
        g_hlo[0][idx] = __float2bfloat16(0.0f);
    }
    if (idx < 64) g_bars[idx] = 0u;
}

__global__ void proj_kernel(const float* __restrict__ letter_emb,
                            const float* __restrict__ state_emb,
                            const float* __restrict__ W_ih,
                            const float* __restrict__ b_ih,
                            const float* __restrict__ b_hh) {
    int idx = blockIdx.x * blockDim.x + threadIdx.x;
    if (idx >= 34 * G4) return;
    int tbl = idx >> 12;
    int c   = idx & (G4 - 1);
    int k = c >> 2, g = c & 3;
    int r = g * H_ + k;
    if (tbl < 30) {
        const float* e = letter_emb + tbl * E_;
        const float* w = W_ih + (size_t)r * (2 * E_);
        float sum = __ldg(b_ih + r) + __ldg(b_hh + r);
        for (int i = 0; i < E_; i++) sum += __ldg(e + i) * __ldg(w + i);
        g_projL[tbl * G4 + c] = sum;
    } else {
        const float* e = state_emb + (tbl - 30) * E_;
        const float* w = W_ih + (size_t)r * (2 * E_) + E_;
        float sum = 0.0f;
        for (int i = 0; i < E_; i++) sum += __ldg(e + i) * __ldg(w + i);
        g_projS[(tbl - 30) * G4 + c] = sum;
    }
}

__global__ void wt_kernel(const float* __restrict__ W_hh) {
    int idx = blockIdx.x * blockDim.x + threadIdx.x;   // over G4*H_
    int c  = idx >> 10;
    int kk = idx & (H_ - 1);
    int k = c >> 2, g = c & 3;
    float w = __ldg(W_hh + (size_t)(g * H_ + k) * H_ + kk);
    __nv_bfloat16 hi = __float2bfloat16(w);
    g_Whi[idx] = hi;
    g_Wlo[idx] = __float2bfloat16(w - __bfloat162float(hi));
}

// ---------------- persistent LSTM kernel (warp-specialized HMMA) -----------
__global__ void __launch_bounds__(384, 1)
lstm_kernel(const int* __restrict__ letter_seq,
            const int* __restrict__ state_seq,
            float* __restrict__ out) {
    extern __shared__ char smem[];
    u32 sb = smem_u32(smem);
    const int t = threadIdx.x;
    const int lane = t & 31;
    const int wid = t >> 5;
    const int bt = blockIdx.x >> 6;
    const int kt = blockIdx.x & 63;
    const int b0 = bt * 128;
    const int c0 = kt * 64;
    const int k0 = kt * 16;

    if (t == 0) {
        MBINIT(sb + SM_FULL0, 128);
        MBINIT(sb + SM_FULL1, 128);
        MBINIT(sb + SM_EMPTY0, 8);
        MBINIT(sb + SM_EMPTY1, 8);
    }

    // preload resident Whi (16 chunks of [64 rows x 64 K] bf16, SW128)
    for (int seg = t; seg < 8192; seg += 384) {
        int ch = seg >> 9;
        int r  = (seg >> 3) & 63;
        int q  = seg & 7;
        CP16(sb + SM_WHI + ch * 8192 + SWZ(r * 128 + q * 16),
             g_Whi + (size_t)(c0 + r) * H_ + ch * 64 + q * 8);
    }
    CP_COMMIT();
    CP_WAIT0();
    __syncthreads();

    if (wid < 8) {
        // ======================= CONSUMER warps =======================
        const int wm = wid & 1;           // M tile: rows 64*wm
        const int wn = wid >> 1;          // N tile: cols 16*wn (4 hidden units)
        const int arow = lane & 15;
        const int asel = (lane >> 4) * 16;
        const int brow = (lane & 7) + ((lane >> 4) & 1) * 8;
        const int bsel = ((lane >> 3) & 1) * 16;
        u32 pF0 = 0, pF1 = 0;
        float cst[8];
#pragma unroll
        for (int j = 0; j < 8; j++) cst[j] = 0.0f;

        const u32 eb = sb + SM_STAGE + wid * EPI_SLAB;   // epilogue slab (buf0)

        for (int s = 0; s < S_; ++s) {
            float D[4][2][4];
#pragma unroll
            for (int a = 0; a < 4; a++)
#pragma unroll
                for (int b = 0; b < 2; b++)
#pragma unroll
                    for (int q = 0; q < 4; q++) D[a][b][q] = 0.0f;

            for (int ch = 0; ch < 16; ++ch) {
                int buf = ch & 1;
                if (buf == 0) { MBWAIT(sb + SM_FULL0, pF0); pF0 ^= 1; }
                else          { MBWAIT(sb + SM_FULL1, pF1); pF1 ^= 1; }
                u32 whib = sb + SM_WHI + ch * 8192;
                u32 stg  = sb + SM_STAGE + buf * STAGE_SZ;
#pragma unroll
                for (int k2 = 0; k2 < 4; ++k2) {
                    int kb = k2 * 32;
                    u32 ahi[4][4], alo[4][4];
#pragma unroll
                    for (int mt = 0; mt < 4; ++mt) {
                        u32 off = SWZ((wm * 64 + mt * 16 + arow) * 128 + kb + asel);
                        LDSM_X4(ahi[mt], stg + OFF_AHI + off);
                        LDSM_X4(alo[mt], stg + OFF_ALO + off);
                    }
                    u32 boff = SWZ((wn * 16 + brow) * 128 + kb + bsel);
                    u32 bhi[2][2], blo[2][2];
                    {
                        u32 r4[4];
                        LDSM_X4(r4, whib + boff);
                        bhi[0][0] = r4[0]; bhi[0][1] = r4[1];
                        bhi[1][0] = r4[2]; bhi[1][1] = r4[3];
                        LDSM_X4(r4, stg + OFF_BLO + boff);
                        blo[0][0] = r4[0]; blo[0][1] = r4[1];
                        blo[1][0] = r4[2]; blo[1][1] = r4[3];
                    }
#pragma unroll
                    for (int mt = 0; mt < 4; ++mt)
#pragma unroll
                        for (int nt = 0; nt < 2; ++nt) {
                            MMA16816(D[mt][nt], ahi[mt], bhi[nt]);
                            MMA16816(D[mt][nt], alo[mt], bhi[nt]);
                            MMA16816(D[mt][nt], ahi[mt], blo[nt]);
                        }
                }
                if (lane == 0)
                    MBARRIVE(sb + (buf ? SM_EMPTY1 : SM_EMPTY0));
            }

            // all consumers done reading buf0 (chunk 14) before slab reuse
            asm volatile("bar.sync 1, 256;" ::: "memory");

            // ---- per-warp epilogue: regs -> slab -> gate math ----
#pragma unroll
            for (int mt = 0; mt < 4; ++mt)
#pragma unroll
                for (int nt = 0; nt < 2; ++nt) {
                    int row0 = mt * 16 + (lane >> 2);
                    u32 a0 = eb + row0 * EPI_STRIDE + (nt * 8 + (lane & 3) * 2) * 4;
                    STS64F(a0, D[mt][nt][0], D[mt][nt][1]);
                    STS64F(a0 + 8 * EPI_STRIDE, D[mt][nt][2], D[mt][nt][3]);
                }
            __syncwarp();

            int par = (s + 1) & 1;
#pragma unroll
            for (int rr = 0; rr < 2; ++rr) {
                int r = lane * 2 + rr;                 // local row 0..63
                int b = b0 + wm * 64 + r;
                int lt = __ldg(letter_seq + b * S_ + s);
                int st = __ldg(state_seq + b * S_ + s);
                const float4* pl = (const float4*)(g_projL + lt * G4 + c0 + wn * 16);
                const float4* ps = (const float4*)(g_projS + st * G4 + c0 + wn * 16);
                float hv[4], cv[4];
                union { __nv_bfloat16 h[4]; uint2 v; } uh, ul;
#pragma unroll
                for (int u = 0; u < 4; ++u) {
                    float4 x;
                    LDS128F(x, eb + r * EPI_STRIDE + u * 16);
                    float4 a = __ldg(pl + u);
                    float4 p = __ldg(ps + u);
                    float xi = x.x + a.x + p.x;
                    float xf = x.y + a.y + p.y;
                    float xg = x.z + a.z + p.z;
                    float xo = x.w + a.w + p.w;
                    float I = sigf(xi), F = sigf(xf), O = sigf(xo), G = tanhfast(xg);
                    float cc = F * cst[rr * 4 + u] + I * G;
                    cst[rr * 4 + u] = cc;
                    float hh = O * tanhfast(cc);
                    hv[u] = hh; cv[u] = cc;
                    __nv_bfloat16 hi16 = __float2bfloat16(hh);
                    uh.h[u] = hi16;
                    ul.h[u] = __float2bfloat16(hh - __bfloat162float(hi16));
                }
                size_t base = (size_t)b * (S_ * H_) + (size_t)s * H_ + k0 + wn * 4;
                *(float4*)(out + base) = make_float4(hv[0], hv[1], hv[2], hv[3]);
                *(float4*)(out + (size_t)B_ * S_ * H_ + base) =
                    make_float4(cv[0], cv[1], cv[2], cv[3]);
                *(uint2*)(&g_hhi[par][b * H_ + k0 + wn * 4]) = uh.v;
                *(uint2*)(&g_hlo[par][b * H_ + k0 + wn * 4]) = ul.v;
            }

            // ---- step-end: block sync + per-bt grid barrier ----
            __syncthreads();
            if (t == 0) {
                __threadfence();
                atomicAdd(&g_bars[bt * 32], 1u);
                u32 target = (u32)(s + 1) * 64u;
                while (*((volatile u32*)&g_bars[bt * 32]) < target) { }
                __threadfence();
            }
            __syncthreads();
        }
    } else {
        // ======================= PRODUCER warps =======================
        const int t2 = t - 256;                      // 0..127
        u32 pE0 = 1, pE1 = 1;

        for (int s = 0; s < S_; ++s) {
            const __nv_bfloat16* hip = g_hhi[s & 1];
            const __nv_bfloat16* lop = g_hlo[s & 1];

            for (int ch = 0; ch < 16; ++ch) {
                int buf = ch & 1;
                if (buf == 0) { MBWAIT(sb + SM_EMPTY0, pE0); pE0 ^= 1; }
                else          { MBWAIT(sb + SM_EMPTY1, pE1); pE1 ^= 1; }
                u32 stg = sb + SM_STAGE + buf * STAGE_SZ;
                int kk0 = ch * 64;
#pragma unroll
                for (int i = 0; i < 8; i++) {        // Ahi: 1024 segs
                    int seg = t2 + 128 * i;
                    int r = seg >> 3, q = seg & 7;
                    CP16(stg + OFF_AHI + SWZ(r * 128 + q * 16),
                         hip + (size_t)(b0 + r) * H_ + kk0 + q * 8);
                }
#pragma unroll
                for (int i = 0; i < 8; i++) {        // Alo
                    int seg = t2 + 128 * i;
                    int r = seg >> 3, q = seg & 7;
                    CP16(stg + OFF_ALO + SWZ(r * 128 + q * 16),
                         lop + (size_t)(b0 + r) * H_ + kk0 + q * 8);
                }
#pragma unroll
                for (int i = 0; i < 4; i++) {        // Blo: 512 segs
                    int seg = t2 + 128 * i;
                    int r = seg >> 3, q = seg & 7;
                    CP16(stg + OFF_BLO + SWZ(r * 128 + q * 16),
                         g_Wlo + (size_t)(c0 + r) * H_ + kk0 + q * 8);
                }
                CP_COMMIT();
                if (ch > 0) {
                    CP_WAIT1();
                    MBARRIVE(sb + ((ch & 1) ? SM_FULL0 : SM_FULL1));  // chunk ch-1
                }
            }
            CP_WAIT0();
            MBARRIVE(sb + SM_FULL1);                 // chunk 15

            __syncthreads();
            // t==0 is a consumer-side thread; producers just pass through
            __syncthreads();
        }
    }
}

// ---------------------------------------------------------------------------
extern "C" void kernel_launch(void* const* d_in, const int* in_sizes, int n_in,
                              void* d_out, int out_size) {
    const int*   letter_seq = (const int*)d_in[0];
    const int*   state_seq  = (const int*)d_in[1];
    const float* letter_emb = (const float*)d_in[2];
    const float* state_emb  = (const float*)d_in[3];
    const float* W_ih       = (const float*)d_in[4];
    const float* W_hh       = (const float*)d_in[5];
    const float* b_ih       = (const float*)d_in[6];
    const float* b_hh       = (const float*)d_in[7];
    float* out = (float*)d_out;

    cudaFuncSetAttribute(lstm_kernel,
                         cudaFuncAttributeMaxDynamicSharedMemorySize, SMEM_TOTAL);

    zero_kernel<<<(B_ * H_ + 255) / 256, 256>>>();
    proj_kernel<<<(34 * G4 + 255) / 256, 256>>>(letter_emb, state_emb, W_ih, b_ih, b_hh);
    wt_kernel<<<((size_t)G4 * H_ + 255) / 256, 256>>>(W_hh);
    lstm_kernel<<<128, 384, SMEM_TOTAL>>>(letter_seq, state_seq, out);
}

// round 7
// speedup vs baseline: 1.8420x; 1.8420x over previous
#include <cuda_runtime.h>
#include <cuda_bf16.h>
#include <cuda_fp16.h>

#define B_  256
#define S_  256
#define E_  256
#define H_  1024
#define G4  4096

typedef unsigned int u32;
typedef unsigned long long u64;

// ---------------- device globals (static, no runtime alloc) ----------------
__device__ float g_projL[30 * G4];
__device__ float g_projS[4 * G4];
__device__ __half g_Wh[(size_t)G4 * H_];     // fp16 W_hh, [c][kk], c = 4k+g
__device__ __half g_h16[2][B_ * H_];         // fp16 hidden state [parity][b*H+k]
__device__ u32 g_bars[64];                   // per-bt barrier (padded)

// ---------------- SMEM layout ----------------
// mbarriers: full[4] @8..40, empty[4] @40..72
// SM_WHI: resident W, 16 chunks x 8192B (SW128 per 64x64 fp16 chunk)
// SM_STAGE: 4-deep ring of A stages (128 rows x 64 kk fp16 = 16KB each)
#define SM_FULL    8
#define SM_EMPTY   40
#define SM_WHI     1024
#define SM_STAGE   132096          // 1024 + 16*8192
#define STAGE_SZ   16384
#define EPI_STRIDE 80
#define EPI_SLAB   5120            // 64 rows * 80B per consumer warp
#define SMEM_TOTAL 197632          // 132096 + 4*16384

#define SWZ(x) ((x) ^ (((x) >> 3) & 0x70))

static __device__ __forceinline__ u32 smem_u32(const void* p) {
    u32 a;
    asm("{ .reg .u64 t; cvta.to.shared.u64 t, %1; cvt.u32.u64 %0, t; }"
        : "=r"(a) : "l"(p));
    return a;
}
#define CP16(dst, src) asm volatile( \
    "cp.async.cg.shared.global [%0], [%1], 16;" :: "r"(dst), "l"(src) : "memory")
#define CP_COMMIT() asm volatile("cp.async.commit_group;" ::: "memory")
#define CP_WAIT0()  asm volatile("cp.async.wait_group 0;" ::: "memory")
#define CP_WAIT1()  asm volatile("cp.async.wait_group 1;" ::: "memory")
#define CP_WAIT2()  asm volatile("cp.async.wait_group 2;" ::: "memory")

#define MBINIT(a, c) asm volatile("mbarrier.init.shared.b64 [%0], %1;" \
    :: "r"(a), "r"((u32)(c)) : "memory")
#define MBARRIVE(a) asm volatile("mbarrier.arrive.shared.b64 _, [%0];" \
    :: "r"(a) : "memory")
#define MBWAIT(addr, par) do {                                                   \
    u32 _a = (addr); u32 _p = (u32)(par); u32 _d;                                \
    asm volatile("{\n\t.reg .pred P;\n\t"                                        \
        "mbarrier.try_wait.parity.acquire.cta.shared::cta.b64 P, [%1], %2;\n\t"  \
        "selp.b32 %0, 1, 0, P;\n\t}"                                             \
        : "=r"(_d) : "r"(_a), "r"(_p) : "memory");                               \
    if (!_d) {                                                                   \
        asm volatile("{\n\t.reg .pred P;\n\t"                                    \
            "WL_%=:\n\t"                                                         \
            "mbarrier.try_wait.parity.acquire.cta.shared::cta.b64 P, [%0], %1, 0x989680;\n\t" \
            "@P bra WD_%=;\n\t"                                                  \
            "bra WL_%=;\n\t"                                                     \
            "WD_%=:\n\t}"                                                        \
            :: "r"(_a), "r"(_p) : "memory");                                     \
    } } while (0)

#define LDSM_X4(r, addr) asm volatile( \
    "ldmatrix.sync.aligned.m8n8.x4.shared.b16 {%0,%1,%2,%3}, [%4];" \
    : "=r"((r)[0]), "=r"((r)[1]), "=r"((r)[2]), "=r"((r)[3]) : "r"(addr))

#define MMAF16(d, a, b) asm volatile( \
    "mma.sync.aligned.m16n8k16.row.col.f32.f16.f16.f32 " \
    "{%0,%1,%2,%3}, {%4,%5,%6,%7}, {%8,%9}, {%0,%1,%2,%3};" \
    : "+f"((d)[0]), "+f"((d)[1]), "+f"((d)[2]), "+f"((d)[3]) \
    : "r"((a)[0]), "r"((a)[1]), "r"((a)[2]), "r"((a)[3]), \
      "r"((b)[0]), "r"((b)[1]))

#define LDS128F(v, addr) asm volatile("ld.shared.v4.f32 {%0,%1,%2,%3}, [%4];" \
    : "=f"((v).x), "=f"((v).y), "=f"((v).z), "=f"((v).w) : "r"(addr))
#define STS64F(addr, x, y) asm volatile("st.shared.v2.f32 [%0], {%1,%2};" \
    :: "r"(addr), "f"(x), "f"(y) : "memory")

static __device__ __forceinline__ float sigf(float x) {
    return __fdividef(1.0f, 1.0f + __expf(-x));
}
static __device__ __forceinline__ float tanhfast(float x) {
    return __fdividef(2.0f, 1.0f + __expf(-2.0f * x)) - 1.0f;
}

// ---------------- prep kernels ----------------
__global__ void zero_kernel() {
    int idx = blockIdx.x * blockDim.x + threadIdx.x;
    if (idx < B_ * H_) g_h16[0][idx] = __float2half(0.0f);
    if (idx < 64) g_bars[idx] = 0u;
}

__global__ void proj_kernel(const float* __restrict__ letter_emb,
                            const float* __restrict__ state_emb,
                            const float* __restrict__ W_ih,
                            const float* __restrict__ b_ih,
                            const float* __restrict__ b_hh) {
    int idx = blockIdx.x * blockDim.x + threadIdx.x;
    if (idx >= 34 * G4) return;
    int tbl = idx >> 12;
    int c   = idx & (G4 - 1);
    int k = c >> 2, g = c & 3;
    int r = g * H_ + k;
    if (tbl < 30) {
        const float* e = letter_emb + tbl * E_;
        const float* w = W_ih + (size_t)r * (2 * E_);
        float sum = __ldg(b_ih + r) + __ldg(b_hh + r);
        for (int i = 0; i < E_; i++) sum += __ldg(e + i) * __ldg(w + i);
        g_projL[tbl * G4 + c] = sum;
    } else {
        const float* e = state_emb + (tbl - 30) * E_;
        const float* w = W_ih + (size_t)r * (2 * E_) + E_;
        float sum = 0.0f;
        for (int i = 0; i < E_; i++) sum += __ldg(e + i) * __ldg(w + i);
        g_projS[(tbl - 30) * G4 + c] = sum;
    }
}

__global__ void wt_kernel(const float* __restrict__ W_hh) {
    int idx = blockIdx.x * blockDim.x + threadIdx.x;   // over G4*H_
    int c  = idx >> 10;
    int kk = idx & (H_ - 1);
    int k = c >> 2, g = c & 3;
    g_Wh[idx] = __float2half(__ldg(W_hh + (size_t)(g * H_ + k) * H_ + kk));
}

// ---------------- persistent LSTM kernel (fp16 1-term HMMA) ----------------
__global__ void __launch_bounds__(384, 1)
lstm_kernel(const int* __restrict__ letter_seq,
            const int* __restrict__ state_seq,
            float* __restrict__ out) {
    extern __shared__ char smem[];
    u32 sb = smem_u32(smem);
    const int t = threadIdx.x;
    const int lane = t & 31;
    const int wid = t >> 5;
    const int bt = blockIdx.x >> 6;
    const int kt = blockIdx.x & 63;
    const int b0 = bt * 128;
    const int c0 = kt * 64;
    const int k0 = kt * 16;

    if (t == 0) {
#pragma unroll
        for (int i = 0; i < 4; i++) {
            MBINIT(sb + SM_FULL + 8 * i, 128);   // producer threads arrive
            MBINIT(sb + SM_EMPTY + 8 * i, 8);    // 8 consumer warps arrive
        }
    }

    // preload resident W (16 chunks of [64 c-rows x 64 kk] fp16, SW128)
    for (int seg = t; seg < 8192; seg += 384) {
        int ch = seg >> 9;
        int r  = (seg >> 3) & 63;
        int q  = seg & 7;
        CP16(sb + SM_WHI + ch * 8192 + SWZ(r * 128 + q * 16),
             g_Wh + (size_t)(c0 + r) * H_ + ch * 64 + q * 8);
    }
    CP_COMMIT();
    CP_WAIT0();
    __syncthreads();

    if (wid < 8) {
        // ======================= CONSUMER warps =======================
        const int wm = wid & 1;            // M tile: rows 64*wm
        const int wn = wid >> 1;           // N tile: cols 16*wn (4 hidden units)
        const int arow = lane & 15;
        const int asel = (lane >> 4) * 16;
        const int brow = (lane & 7) + ((lane >> 4) & 1) * 8;
        const int bsel = ((lane >> 3) & 1) * 16;
        u32 fphase = 0;                    // full-ring cursor phase
        float cst[8];
#pragma unroll
        for (int j = 0; j < 8; j++) cst[j] = 0.0f;

        const u32 eb = sb + SM_STAGE + wid * EPI_SLAB;

        for (int s = 0; s < S_; ++s) {
            float D[4][2][4];
#pragma unroll
            for (int a = 0; a < 4; a++)
#pragma unroll
                for (int b = 0; b < 2; b++)
#pragma unroll
                    for (int q = 0; q < 4; q++) D[a][b][q] = 0.0f;

            for (int ch = 0; ch < 16; ++ch) {
                int st = ch & 3;
                MBWAIT(sb + SM_FULL + 8 * st, fphase);
                if (st == 3) fphase ^= 1;
                u32 whib = sb + SM_WHI + ch * 8192;
                u32 stg  = sb + SM_STAGE + st * STAGE_SZ;
#pragma unroll
                for (int k2 = 0; k2 < 4; ++k2) {
                    int kb = k2 * 32;
                    u32 ah[4][4];
#pragma unroll
                    for (int mt = 0; mt < 4; ++mt) {
                        u32 off = SWZ((wm * 64 + mt * 16 + arow) * 128 + kb + asel);
                        LDSM_X4(ah[mt], stg + off);
                    }
                    u32 bh[2][2];
                    {
                        u32 r4[4];
                        u32 boff = SWZ((wn * 16 + brow) * 128 + kb + bsel);
                        LDSM_X4(r4, whib + boff);
                        bh[0][0] = r4[0]; bh[0][1] = r4[1];
                        bh[1][0] = r4[2]; bh[1][1] = r4[3];
                    }
#pragma unroll
                    for (int mt = 0; mt < 4; ++mt)
#pragma unroll
                        for (int nt = 0; nt < 2; ++nt)
                            MMAF16(D[mt][nt], ah[mt], bh[nt]);
                }
                if (lane == 0)
                    MBARRIVE(sb + SM_EMPTY + 8 * st);
            }

            // all consumers finished reading stage ring before slab reuse
            asm volatile("bar.sync 1, 256;" ::: "memory");

            // ---- per-warp epilogue: regs -> slab -> gate math ----
#pragma unroll
            for (int mt = 0; mt < 4; ++mt)
#pragma unroll
                for (int nt = 0; nt < 2; ++nt) {
                    int row0 = mt * 16 + (lane >> 2);
                    u32 a0 = eb + row0 * EPI_STRIDE + (nt * 8 + (lane & 3) * 2) * 4;
                    STS64F(a0, D[mt][nt][0], D[mt][nt][1]);
                    STS64F(a0 + 8 * EPI_STRIDE, D[mt][nt][2], D[mt][nt][3]);
                }
            __syncwarp();

            int par = (s + 1) & 1;
#pragma unroll
            for (int rr = 0; rr < 2; ++rr) {
                int r = lane * 2 + rr;                 // local row 0..63
                int b = b0 + wm * 64 + r;
                int lt = __ldg(letter_seq + b * S_ + s);
                int stt = __ldg(state_seq + b * S_ + s);
                const float4* pl = (const float4*)(g_projL + lt * G4 + c0 + wn * 16);
                const float4* ps = (const float4*)(g_projS + stt * G4 + c0 + wn * 16);
                float hv[4], cv[4];
                union { __half h[4]; uint2 v; } uh;
#pragma unroll
                for (int u = 0; u < 4; ++u) {
                    float4 x;
                    LDS128F(x, eb + r * EPI_STRIDE + u * 16);
                    float4 a = __ldg(pl + u);
                    float4 p = __ldg(ps + u);
                    float xi = x.x + a.x + p.x;
                    float xf = x.y + a.y + p.y;
                    float xg = x.z + a.z + p.z;
                    float xo = x.w + a.w + p.w;
                    float I = sigf(xi), F = sigf(xf), O = sigf(xo), G = tanhfast(xg);
                    float cc = F * cst[rr * 4 + u] + I * G;
                    cst[rr * 4 + u] = cc;
                    float hh = O * tanhfast(cc);
                    hv[u] = hh; cv[u] = cc;
                    uh.h[u] = __float2half(hh);
                }
                size_t base = (size_t)b * (S_ * H_) + (size_t)s * H_ + k0 + wn * 4;
                *(float4*)(out + base) = make_float4(hv[0], hv[1], hv[2], hv[3]);
                *(float4*)(out + (size_t)B_ * S_ * H_ + base) =
                    make_float4(cv[0], cv[1], cv[2], cv[3]);
                *(uint2*)(&g_h16[par][b * H_ + k0 + wn * 4]) = uh.v;
            }

            // ---- step-end: block sync + per-bt grid barrier ----
            __syncthreads();
            if (t == 0) {
                __threadfence();
                atomicAdd(&g_bars[bt * 32], 1u);
                u32 target = (u32)(s + 1) * 64u;
                while (*((volatile u32*)&g_bars[bt * 32]) < target) { }
                __threadfence();
            }
            __syncthreads();
        }
    } else {
        // ======================= PRODUCER warps =======================
        const int t2 = t - 256;                      // 0..127
        u32 ephase = 1;                              // fresh-barrier trick

        for (int s = 0; s < S_; ++s) {
            const __half* hp = g_h16[s & 1];

            for (int ch = 0; ch < 16; ++ch) {
                int st = ch & 3;
                MBWAIT(sb + SM_EMPTY + 8 * st, ephase);
                if (st == 3) ephase ^= 1;
                u32 stg = sb + SM_STAGE + st * STAGE_SZ;
                int kk0 = ch * 64;
#pragma unroll
                for (int i = 0; i < 8; i++) {        // 1024 16B segs
                    int seg = t2 + 128 * i;
                    int r = seg >> 3, q = seg & 7;
                    CP16(stg + SWZ(r * 128 + q * 16),
                         hp + (size_t)(b0 + r) * H_ + kk0 + q * 8);
                }
                CP_COMMIT();
                if (ch >= 2) {
                    CP_WAIT2();                      // chunk ch-2 landed
                    MBARRIVE(sb + SM_FULL + 8 * ((ch - 2) & 3));
                }
            }
            CP_WAIT1();
            MBARRIVE(sb + SM_FULL + 8 * 2);          // chunk 14
            CP_WAIT0();
            MBARRIVE(sb + SM_FULL + 8 * 3);          // chunk 15

            __syncthreads();                         // step-end sync (pair 1)
            __syncthreads();                         // step-end sync (pair 2)
        }
    }
}

// ---------------------------------------------------------------------------
extern "C" void kernel_launch(void* const* d_in, const int* in_sizes, int n_in,
                              void* d_out, int out_size) {
    const int*   letter_seq = (const int*)d_in[0];
    const int*   state_seq  = (const int*)d_in[1];
    const float* letter_emb = (const float*)d_in[2];
    const float* state_emb  = (const float*)d_in[3];
    const float* W_ih       = (const float*)d_in[4];
    const float* W_hh       = (const float*)d_in[5];
    const float* b_ih       = (const float*)d_in[6];
    const float* b_hh       = (const float*)d_in[7];
    float* out = (float*)d_out;

    cudaFuncSetAttribute(lstm_kernel,
                         cudaFuncAttributeMaxDynamicSharedMemorySize, SMEM_TOTAL);

    zero_kernel<<<(B_ * H_ + 255) / 256, 256>>>();
    proj_kernel<<<(34 * G4 + 255) / 256, 256>>>(letter_emb, state_emb, W_ih, b_ih, b_hh);
    wt_kernel<<<((size_t)G4 * H_ + 255) / 256, 256>>>(W_hh);
    lstm_kernel<<<128, 384, SMEM_TOTAL>>>(letter_seq, state_seq, out);
}

// round 8
// speedup vs baseline: 2.0151x; 1.0940x over previous
#include <cuda_runtime.h>
#include <cuda_fp16.h>

#define B_  256
#define S_  256
#define E_  256
#define H_  1024
#define G4  4096

typedef unsigned int u32;
typedef unsigned long long u64;

// ---------------- device globals (static, no runtime alloc) ----------------
__device__ float g_projL[30 * G4];
__device__ float g_projS[4 * G4];
__device__ __half g_Wh[(size_t)G4 * H_];     // fp16 W_hh, [c][kk], c = 4k+g
__device__ __half g_h16[2][B_ * H_];         // fp16 hidden state [parity][b*H+k]
__device__ u32 g_bars[64];                   // per-bt barrier (padded)

// ---------------- SMEM layout ----------------
// mbarriers: full[4] @8..40, empty[4] @40..72
// SM_WHI: resident W, 16 chunks x 8192B (SW128 per 64x64 fp16 chunk)
// SM_STAGE: 4-deep ring of A stages (128 rows x 64 kk fp16 = 16KB each)
//           reused at step end as the D slab (128 rows x 272B = 34816B)
#define SM_FULL    8
#define SM_EMPTY   40
#define SM_WHI     1024
#define SM_STAGE   132096          // 1024 + 16*8192
#define STAGE_SZ   16384
#define SLAB_STRIDE 272            // 64 f32 + 16B pad per row
#define SMEM_TOTAL 197632          // 132096 + 4*16384

#define SWZ(x) ((x) ^ (((x) >> 3) & 0x70))

static __device__ __forceinline__ u32 smem_u32(const void* p) {
    u32 a;
    asm("{ .reg .u64 t; cvta.to.shared.u64 t, %1; cvt.u32.u64 %0, t; }"
        : "=r"(a) : "l"(p));
    return a;
}
#define CP16(dst, src) asm volatile( \
    "cp.async.cg.shared.global [%0], [%1], 16;" :: "r"(dst), "l"(src) : "memory")
#define CP_COMMIT() asm volatile("cp.async.commit_group;" ::: "memory")
#define CP_WAIT0()  asm volatile("cp.async.wait_group 0;" ::: "memory")
#define CP_WAIT1()  asm volatile("cp.async.wait_group 1;" ::: "memory")
#define CP_WAIT2()  asm volatile("cp.async.wait_group 2;" ::: "memory")

#define MBINIT(a, c) asm volatile("mbarrier.init.shared.b64 [%0], %1;" \
    :: "r"(a), "r"((u32)(c)) : "memory")
#define MBARRIVE(a) asm volatile("mbarrier.arrive.shared.b64 _, [%0];" \
    :: "r"(a) : "memory")
#define MBWAIT(addr, par) do {                                                   \
    u32 _a = (addr); u32 _p = (u32)(par); u32 _d;                                \
    asm volatile("{\n\t.reg .pred P;\n\t"                                        \
        "mbarrier.try_wait.parity.acquire.cta.shared::cta.b64 P, [%1], %2;\n\t"  \
        "selp.b32 %0, 1, 0, P;\n\t}"                                             \
        : "=r"(_d) : "r"(_a), "r"(_p) : "memory");                               \
    if (!_d) {                                                                   \
        asm volatile("{\n\t.reg .pred P;\n\t"                                    \
            "WL_%=:\n\t"                                                         \
            "mbarrier.try_wait.parity.acquire.cta.shared::cta.b64 P, [%0], %1, 0x989680;\n\t" \
            "@P bra WD_%=;\n\t"                                                  \
            "bra WL_%=;\n\t"                                                     \
            "WD_%=:\n\t}"                                                        \
            :: "r"(_a), "r"(_p) : "memory");                                     \
    } } while (0)

#define LDSM_X4(r, addr) asm volatile( \
    "ldmatrix.sync.aligned.m8n8.x4.shared.b16 {%0,%1,%2,%3}, [%4];" \
    : "=r"((r)[0]), "=r"((r)[1]), "=r"((r)[2]), "=r"((r)[3]) : "r"(addr))

#define MMAF16(d, a, b) asm volatile( \
    "mma.sync.aligned.m16n8k16.row.col.f32.f16.f16.f32 " \
    "{%0,%1,%2,%3}, {%4,%5,%6,%7}, {%8,%9}, {%0,%1,%2,%3};" \
    : "+f"((d)[0]), "+f"((d)[1]), "+f"((d)[2]), "+f"((d)[3]) \
    : "r"((a)[0]), "r"((a)[1]), "r"((a)[2]), "r"((a)[3]), \
      "r"((b)[0]), "r"((b)[1]))

#define LDS128F(v, addr) asm volatile("ld.shared.v4.f32 {%0,%1,%2,%3}, [%4];" \
    : "=f"((v).x), "=f"((v).y), "=f"((v).z), "=f"((v).w) : "r"(addr))
#define STS64F(addr, x, y) asm volatile("st.shared.v2.f32 [%0], {%1,%2};" \
    :: "r"(addr), "f"(x), "f"(y) : "memory")

static __device__ __forceinline__ float sigf(float x) {
    return __fdividef(1.0f, 1.0f + __expf(-x));
}
static __device__ __forceinline__ float tanhfast(float x) {
    return __fdividef(2.0f, 1.0f + __expf(-2.0f * x)) - 1.0f;
}

// ---------------- prep kernels ----------------
__global__ void zero_kernel() {
    int idx = blockIdx.x * blockDim.x + threadIdx.x;
    if (idx < B_ * H_) g_h16[0][idx] = __float2half(0.0f);
    if (idx < 64) g_bars[idx] = 0u;
}

__global__ void proj_kernel(const float* __restrict__ letter_emb,
                            const float* __restrict__ state_emb,
                            const float* __restrict__ W_ih,
                            const float* __restrict__ b_ih,
                            const float* __restrict__ b_hh) {
    int idx = blockIdx.x * blockDim.x + threadIdx.x;
    if (idx >= 34 * G4) return;
    int tbl = idx >> 12;
    int c   = idx & (G4 - 1);
    int k = c >> 2, g = c & 3;
    int r = g * H_ + k;
    if (tbl < 30) {
        const float* e = letter_emb + tbl * E_;
        const float* w = W_ih + (size_t)r * (2 * E_);
        float sum = __ldg(b_ih + r) + __ldg(b_hh + r);
        for (int i = 0; i < E_; i++) sum += __ldg(e + i) * __ldg(w + i);
        g_projL[tbl * G4 + c] = sum;
    } else {
        const float* e = state_emb + (tbl - 30) * E_;
        const float* w = W_ih + (size_t)r * (2 * E_) + E_;
        float sum = 0.0f;
        for (int i = 0; i < E_; i++) sum += __ldg(e + i) * __ldg(w + i);
        g_projS[(tbl - 30) * G4 + c] = sum;
    }
}

__global__ void wt_kernel(const float* __restrict__ W_hh) {
    int idx = blockIdx.x * blockDim.x + threadIdx.x;   // over G4*H_
    int c  = idx >> 10;
    int kk = idx & (H_ - 1);
    int k = c >> 2, g = c & 3;
    g_Wh[idx] = __float2half(__ldg(W_hh + (size_t)(g * H_ + k) * H_ + kk));
}

// ---------------- persistent LSTM kernel (fp16 HMMA, 2x2 warp grid) --------
__global__ void __launch_bounds__(384, 1)
lstm_kernel(const int* __restrict__ letter_seq,
            const int* __restrict__ state_seq,
            float* __restrict__ out) {
    extern __shared__ char smem[];
    u32 sb = smem_u32(smem);
    const int t = threadIdx.x;
    const int lane = t & 31;
    const int wid = t >> 5;
    const int bt = blockIdx.x >> 6;
    const int kt = blockIdx.x & 63;
    const int b0 = bt * 128;
    const int c0 = kt * 64;
    const int k0 = kt * 16;

    if (t == 0) {
#pragma unroll
        for (int i = 0; i < 4; i++) {
            MBINIT(sb + SM_FULL + 8 * i, 256);   // 256 producer threads arrive
            MBINIT(sb + SM_EMPTY + 8 * i, 4);    // 4 consumer warps arrive
        }
    }

    // preload resident W (16 chunks of [64 c-rows x 64 kk] fp16, SW128)
    for (int seg = t; seg < 8192; seg += 384) {
        int ch = seg >> 9;
        int r  = (seg >> 3) & 63;
        int q  = seg & 7;
        CP16(sb + SM_WHI + ch * 8192 + SWZ(r * 128 + q * 16),
             g_Wh + (size_t)(c0 + r) * H_ + ch * 64 + q * 8);
    }
    CP_COMMIT();
    CP_WAIT0();
    __syncthreads();

    if (wid < 4) {
        // ============== CONSUMER warps (2M x 2N, tile M64 x N32) ==============
        const int wm = wid & 1;            // rows 64*wm .. +64
        const int wn = wid >> 1;           // cols 32*wn .. +32
        const int arow = lane & 15;
        const int asel = (lane >> 4) * 16;
        const int brow = (lane & 7) + ((lane >> 4) & 1) * 8;
        const int bsel = ((lane >> 3) & 1) * 16;
        u32 fphase = 0;
        float cst[16];
#pragma unroll
        for (int j = 0; j < 16; j++) cst[j] = 0.0f;

        const u32 slab = sb + SM_STAGE;

        for (int s = 0; s < S_; ++s) {
            float D[4][4][4];
#pragma unroll
            for (int a = 0; a < 4; a++)
#pragma unroll
                for (int b = 0; b < 4; b++)
#pragma unroll
                    for (int q = 0; q < 4; q++) D[a][b][q] = 0.0f;

            for (int ch = 0; ch < 16; ++ch) {
                int st = ch & 3;
                MBWAIT(sb + SM_FULL + 8 * st, fphase);
                if (st == 3) fphase ^= 1;
                u32 whib = sb + SM_WHI + ch * 8192;
                u32 stg  = sb + SM_STAGE + st * STAGE_SZ;
#pragma unroll
                for (int k2 = 0; k2 < 4; ++k2) {
                    int kb = k2 * 32;
                    u32 ah[4][4];
#pragma unroll
                    for (int mt = 0; mt < 4; ++mt) {
                        u32 off = SWZ((wm * 64 + mt * 16 + arow) * 128 + kb + asel);
                        LDSM_X4(ah[mt], stg + off);
                    }
                    u32 bh[4][2];
#pragma unroll
                    for (int nb = 0; nb < 2; ++nb) {
                        u32 r4[4];
                        u32 boff = SWZ((wn * 32 + nb * 16 + brow) * 128 + kb + bsel);
                        LDSM_X4(r4, whib + boff);
                        bh[2 * nb][0] = r4[0]; bh[2 * nb][1] = r4[1];
                        bh[2 * nb + 1][0] = r4[2]; bh[2 * nb + 1][1] = r4[3];
                    }
#pragma unroll
                    for (int mt = 0; mt < 4; ++mt)
#pragma unroll
                        for (int nt = 0; nt < 4; ++nt)
                            MMAF16(D[mt][nt], ah[mt], bh[nt]);
                }
                if (lane == 0)
                    MBARRIVE(sb + SM_EMPTY + 8 * st);
            }

            // ring fully consumed by all consumer warps before slab overwrite
            asm volatile("bar.sync 1, 128;" ::: "memory");

            // ---- D regs -> common slab [128 rows][64 cols f32] ----
#pragma unroll
            for (int mt = 0; mt < 4; ++mt)
#pragma unroll
                for (int nt = 0; nt < 4; ++nt) {
                    int row0 = wm * 64 + mt * 16 + (lane >> 2);
                    int col  = wn * 32 + nt * 8 + (lane & 3) * 2;
                    u32 a0 = slab + row0 * SLAB_STRIDE + col * 4;
                    STS64F(a0, D[mt][nt][0], D[mt][nt][1]);
                    STS64F(a0 + 8 * SLAB_STRIDE, D[mt][nt][2], D[mt][nt][3]);
                }
            asm volatile("bar.sync 1, 128;" ::: "memory");

            // ---- epilogue: thread t owns batch row b0+t (16 hidden units) ----
            {
                int b = b0 + t;
                int lt  = __ldg(letter_seq + b * S_ + s);
                int stt = __ldg(state_seq + b * S_ + s);
                const float4* pl = (const float4*)(g_projL + lt * G4 + c0);
                const float4* ps = (const float4*)(g_projS + stt * G4 + c0);
                u32 rowp = slab + t * SLAB_STRIDE;
                float hv[16], cv[16];
                union { __half h[16]; int4 v[2]; } uh;
#pragma unroll
                for (int u = 0; u < 16; ++u) {
                    float4 x;
                    LDS128F(x, rowp + u * 16);
                    float4 a = __ldg(pl + u);
                    float4 p = __ldg(ps + u);
                    float xi = x.x + a.x + p.x;
                    float xf = x.y + a.y + p.y;
                    float xg = x.z + a.z + p.z;
                    float xo = x.w + a.w + p.w;
                    float I = sigf(xi), F = sigf(xf), O = sigf(xo), G = tanhfast(xg);
                    float cc = F * cst[u] + I * G;
                    cst[u] = cc;
                    float hh = O * tanhfast(cc);
                    hv[u] = hh; cv[u] = cc;
                    uh.h[u] = __float2half(hh);
                }
                size_t base = (size_t)b * (S_ * H_) + (size_t)s * H_ + k0;
                float4* po = (float4*)(out + base);
                float4* pc = (float4*)(out + (size_t)B_ * S_ * H_ + base);
#pragma unroll
                for (int q = 0; q < 4; q++) {
                    po[q] = make_float4(hv[4*q], hv[4*q+1], hv[4*q+2], hv[4*q+3]);
                    pc[q] = make_float4(cv[4*q], cv[4*q+1], cv[4*q+2], cv[4*q+3]);
                }
                int par = (s + 1) & 1;
                *(int4*)(&g_h16[par][b * H_ + k0])     = uh.v[0];
                *(int4*)(&g_h16[par][b * H_ + k0 + 8]) = uh.v[1];
            }

            // ---- step-end: block sync + per-bt grid barrier ----
            __syncthreads();
            if (t == 0) {
                __threadfence();
                atomicAdd(&g_bars[bt * 32], 1u);
                u32 target = (u32)(s + 1) * 64u;
                while (*((volatile u32*)&g_bars[bt * 32]) < target) { }
                __threadfence();
            }
            __syncthreads();
        }
    } else {
        // ======================= PRODUCER warps (8) =======================
        const int t2 = t - 128;                      // 0..255
        u32 ephase = 1;                              // fresh-barrier trick

        for (int s = 0; s < S_; ++s) {
            const __half* hp = g_h16[s & 1];

            for (int ch = 0; ch < 16; ++ch) {
                int st = ch & 3;
                MBWAIT(sb + SM_EMPTY + 8 * st, ephase);
                if (st == 3) ephase ^= 1;
                u32 stg = sb + SM_STAGE + st * STAGE_SZ;
                int kk0 = ch * 64;
#pragma unroll
                for (int i = 0; i < 4; i++) {        // 1024 16B segs / 256 thr
                    int seg = t2 + 256 * i;
                    int r = seg >> 3, q = seg & 7;
                    CP16(stg + SWZ(r * 128 + q * 16),
                         hp + (size_t)(b0 + r) * H_ + kk0 + q * 8);
                }
                CP_COMMIT();
                if (ch >= 2) {
                    CP_WAIT2();                      // chunk ch-2 landed
                    MBARRIVE(sb + SM_FULL + 8 * ((ch - 2) & 3));
                }
            }
            CP_WAIT1();
            MBARRIVE(sb + SM_FULL + 8 * 2);          // chunk 14
            CP_WAIT0();
            MBARRIVE(sb + SM_FULL + 8 * 3);          // chunk 15

            __syncthreads();                         // step-end sync (pair 1)
            __syncthreads();                         // step-end sync (pair 2)
        }
    }
}

// ---------------------------------------------------------------------------
extern "C" void kernel_launch(void* const* d_in, const int* in_sizes, int n_in,
                              void* d_out, int out_size) {
    const int*   letter_seq = (const int*)d_in[0];
    const int*   state_seq  = (const int*)d_in[1];
    const float* letter_emb = (const float*)d_in[2];
    const float* state_emb  = (const float*)d_in[3];
    const float* W_ih       = (const float*)d_in[4];
    const float* W_hh       = (const float*)d_in[5];
    const float* b_ih       = (const float*)d_in[6];
    const float* b_hh       = (const float*)d_in[7];
    float* out = (float*)d_out;

    cudaFuncSetAttribute(lstm_kernel,
                         cudaFuncAttributeMaxDynamicSharedMemorySize, SMEM_TOTAL);

    zero_kernel<<<(B_ * H_ + 255) / 256, 256>>>();
    proj_kernel<<<(34 * G4 + 255) / 256, 256>>>(letter_emb, state_emb, W_ih, b_ih, b_hh);
    wt_kernel<<<((size_t)G4 * H_ + 255) / 256, 256>>>(W_hh);
    lstm_kernel<<<128, 384, SMEM_TOTAL>>>(letter_seq, state_seq, out);
}

// round 9
// speedup vs baseline: 2.1829x; 1.0833x over previous
#include <cuda_runtime.h>
#include <cuda_fp16.h>

#define B_  256
#define S_  256
#define E_  256
#define H_  1024
#define G4  4096

typedef unsigned int u32;
typedef unsigned long long u64;

// ---------------- device globals (static, no runtime alloc) ----------------
__device__ float g_projL[30 * G4];
__device__ float g_projS[4 * G4];
__device__ __half g_Wh[(size_t)G4 * H_];     // fp16 W_hh, [c][kk], c = 4k+g
__device__ __half g_h16[2][B_ * H_];         // fp16 hidden state [parity][b*H+k]
__device__ u32 g_bars[64];                   // per-bt barrier (padded)

// ---------------- SMEM layout ----------------
// mbarriers: full[4] @8..40, empty[4] @40..72
// SM_WHI: resident W, 16 chunks x 8192B (SW128 per 64x64 fp16 chunk)
// SM_STAGE: 4-deep ring of A stages (16KB each); after the mainloop the same
//           region is reused as TWO D slabs (one per K-group) for reduction.
#define SM_FULL     8
#define SM_EMPTY    40
#define SM_WHI      1024
#define SM_STAGE    132096         // 1024 + 16*8192
#define STAGE_SZ    16384
#define SLAB_STRIDE 272            // 64 f32 + 16B pad per row
#define SLAB_HALF   34816          // 128 * 272
#define SMEM_TOTAL  201728         // 132096 + 2*34816

#define SWZ(x) ((x) ^ (((x) >> 3) & 0x70))

static __device__ __forceinline__ u32 smem_u32(const void* p) {
    u32 a;
    asm("{ .reg .u64 t; cvta.to.shared.u64 t, %1; cvt.u32.u64 %0, t; }"
        : "=r"(a) : "l"(p));
    return a;
}
#define CP16(dst, src) asm volatile( \
    "cp.async.cg.shared.global [%0], [%1], 16;" :: "r"(dst), "l"(src) : "memory")
#define CP_COMMIT() asm volatile("cp.async.commit_group;" ::: "memory")
#define CP_WAIT0()  asm volatile("cp.async.wait_group 0;" ::: "memory")
#define CP_WAIT1()  asm volatile("cp.async.wait_group 1;" ::: "memory")
#define CP_WAIT2()  asm volatile("cp.async.wait_group 2;" ::: "memory")

#define MBINIT(a, c) asm volatile("mbarrier.init.shared.b64 [%0], %1;" \
    :: "r"(a), "r"((u32)(c)) : "memory")
#define MBARRIVE(a) asm volatile("mbarrier.arrive.shared.b64 _, [%0];" \
    :: "r"(a) : "memory")
#define MBWAIT(addr, par) do {                                                   \
    u32 _a = (addr); u32 _p = (u32)(par); u32 _d;                                \
    asm volatile("{\n\t.reg .pred P;\n\t"                                        \
        "mbarrier.try_wait.parity.acquire.cta.shared::cta.b64 P, [%1], %2;\n\t"  \
        "selp.b32 %0, 1, 0, P;\n\t}"                                             \
        : "=r"(_d) : "r"(_a), "r"(_p) : "memory");                               \
    if (!_d) {                                                                   \
        asm volatile("{\n\t.reg .pred P;\n\t"                                    \
            "WL_%=:\n\t"                                                         \
            "mbarrier.try_wait.parity.acquire.cta.shared::cta.b64 P, [%0], %1, 0x989680;\n\t" \
            "@P bra WD_%=;\n\t"                                                  \
            "bra WL_%=;\n\t"                                                     \
            "WD_%=:\n\t}"                                                        \
            :: "r"(_a), "r"(_p) : "memory");                                     \
    } } while (0)

#define LDSM_X4(r, addr) asm volatile( \
    "ldmatrix.sync.aligned.m8n8.x4.shared.b16 {%0,%1,%2,%3}, [%4];" \
    : "=r"((r)[0]), "=r"((r)[1]), "=r"((r)[2]), "=r"((r)[3]) : "r"(addr))

#define MMAF16(d, a, b) asm volatile( \
    "mma.sync.aligned.m16n8k16.row.col.f32.f16.f16.f32 " \
    "{%0,%1,%2,%3}, {%4,%5,%6,%7}, {%8,%9}, {%0,%1,%2,%3};" \
    : "+f"((d)[0]), "+f"((d)[1]), "+f"((d)[2]), "+f"((d)[3]) \
    : "r"((a)[0]), "r"((a)[1]), "r"((a)[2]), "r"((a)[3]), \
      "r"((b)[0]), "r"((b)[1]))

#define LDS128F(v, addr) asm volatile("ld.shared.v4.f32 {%0,%1,%2,%3}, [%4];" \
    : "=f"((v).x), "=f"((v).y), "=f"((v).z), "=f"((v).w) : "r"(addr))
#define STS64F(addr, x, y) asm volatile("st.shared.v2.f32 [%0], {%1,%2};" \
    :: "r"(addr), "f"(x), "f"(y) : "memory")

static __device__ __forceinline__ float sigf(float x) {
    return __fdividef(1.0f, 1.0f + __expf(-x));
}
static __device__ __forceinline__ float tanhfast(float x) {
    return __fdividef(2.0f, 1.0f + __expf(-2.0f * x)) - 1.0f;
}

// ---------------- prep kernels ----------------
__global__ void zero_kernel() {
    int idx = blockIdx.x * blockDim.x + threadIdx.x;
    if (idx < B_ * H_) g_h16[0][idx] = __float2half(0.0f);
    if (idx < 64) g_bars[idx] = 0u;
}

__global__ void proj_kernel(const float* __restrict__ letter_emb,
                            const float* __restrict__ state_emb,
                            const float* __restrict__ W_ih,
                            const float* __restrict__ b_ih,
                            const float* __restrict__ b_hh) {
    int idx = blockIdx.x * blockDim.x + threadIdx.x;
    if (idx >= 34 * G4) return;
    int tbl = idx >> 12;
    int c   = idx & (G4 - 1);
    int k = c >> 2, g = c & 3;
    int r = g * H_ + k;
    if (tbl < 30) {
        const float* e = letter_emb + tbl * E_;
        const float* w = W_ih + (size_t)r * (2 * E_);
        float sum = __ldg(b_ih + r) + __ldg(b_hh + r);
        for (int i = 0; i < E_; i++) sum += __ldg(e + i) * __ldg(w + i);
        g_projL[tbl * G4 + c] = sum;
    } else {
        const float* e = state_emb + (tbl - 30) * E_;
        const float* w = W_ih + (size_t)r * (2 * E_) + E_;
        float sum = 0.0f;
        for (int i = 0; i < E_; i++) sum += __ldg(e + i) * __ldg(w + i);
        g_projS[(tbl - 30) * G4 + c] = sum;
    }
}

__global__ void wt_kernel(const float* __restrict__ W_hh) {
    int idx = blockIdx.x * blockDim.x + threadIdx.x;   // over G4*H_
    int c  = idx >> 10;
    int kk = idx & (H_ - 1);
    int k = c >> 2, g = c & 3;
    g_Wh[idx] = __float2half(__ldg(W_hh + (size_t)(g * H_ + k) * H_ + kk));
}

// ------- persistent LSTM kernel (fp16 HMMA, 2M x 2N x 2K warp grid) --------
__global__ void __launch_bounds__(384, 1)
lstm_kernel(const int* __restrict__ letter_seq,
            const int* __restrict__ state_seq,
            float* __restrict__ out) {
    extern __shared__ char smem[];
    u32 sb = smem_u32(smem);
    const int t = threadIdx.x;
    const int lane = t & 31;
    const int wid = t >> 5;
    const int bt = blockIdx.x >> 6;
    const int kt = blockIdx.x & 63;
    const int b0 = bt * 128;
    const int c0 = kt * 64;
    const int k0 = kt * 16;

    if (t == 0) {
#pragma unroll
        for (int i = 0; i < 4; i++) {
            MBINIT(sb + SM_FULL + 8 * i, 128);   // 128 producer threads arrive
            MBINIT(sb + SM_EMPTY + 8 * i, 4);    // 4 consumer warps (per K-group)
        }
    }

    // preload resident W (16 chunks of [64 c-rows x 64 kk] fp16, SW128)
    for (int seg = t; seg < 8192; seg += 384) {
        int ch = seg >> 9;
        int r  = (seg >> 3) & 63;
        int q  = seg & 7;
        CP16(sb + SM_WHI + ch * 8192 + SWZ(r * 128 + q * 16),
             g_Wh + (size_t)(c0 + r) * H_ + ch * 64 + q * 8);
    }
    CP_COMMIT();
    CP_WAIT0();
    __syncthreads();

    if (wid < 8) {
        // ===== CONSUMER warps: 2M x 2N x 2K, warp tile M64 x N32, K parity ====
        const int wm = wid & 1;            // rows 64*wm .. +64
        const int wn = (wid >> 1) & 1;     // cols 32*wn .. +32
        const int wk = wid >> 2;           // K-chunk parity (0=even, 1=odd)
        const int arow = lane & 15;
        const int asel = (lane >> 4) * 16;
        const int brow = (lane & 7) + ((lane >> 4) & 1) * 8;
        const int bsel = ((lane >> 3) & 1) * 16;
        u32 ph[2] = {0, 0};                // phase per owned stage (wk, wk+2)
        float cst[8];
#pragma unroll
        for (int j = 0; j < 8; j++) cst[j] = 0.0f;

        const u32 myslab = sb + SM_STAGE + wk * SLAB_HALF;

        for (int s = 0; s < S_; ++s) {
            float D[4][4][4];
#pragma unroll
            for (int a = 0; a < 4; a++)
#pragma unroll
                for (int b = 0; b < 4; b++)
#pragma unroll
                    for (int q = 0; q < 4; q++) D[a][b][q] = 0.0f;

            for (int ch = wk; ch < 16; ch += 2) {
                int st = ch & 3;
                int pi = st >> 1;
                MBWAIT(sb + SM_FULL + 8 * st, ph[pi]);
                ph[pi] ^= 1;
                u32 whib = sb + SM_WHI + ch * 8192;
                u32 stg  = sb + SM_STAGE + st * STAGE_SZ;
#pragma unroll
                for (int k2 = 0; k2 < 4; ++k2) {
                    int kb = k2 * 32;
                    u32 ah[4][4];
#pragma unroll
                    for (int mt = 0; mt < 4; ++mt) {
                        u32 off = SWZ((wm * 64 + mt * 16 + arow) * 128 + kb + asel);
                        LDSM_X4(ah[mt], stg + off);
                    }
                    u32 bh[4][2];
#pragma unroll
                    for (int nb = 0; nb < 2; ++nb) {
                        u32 r4[4];
                        u32 boff = SWZ((wn * 32 + nb * 16 + brow) * 128 + kb + bsel);
                        LDSM_X4(r4, whib + boff);
                        bh[2 * nb][0] = r4[0]; bh[2 * nb][1] = r4[1];
                        bh[2 * nb + 1][0] = r4[2]; bh[2 * nb + 1][1] = r4[3];
                    }
#pragma unroll
                    for (int mt = 0; mt < 4; ++mt)
#pragma unroll
                        for (int nt = 0; nt < 4; ++nt)
                            MMAF16(D[mt][nt], ah[mt], bh[nt]);
                }
                if (lane == 0)
                    MBARRIVE(sb + SM_EMPTY + 8 * st);
            }

            // all consumers done reading the ring before it becomes the D slabs
            asm volatile("bar.sync 1, 256;" ::: "memory");

            // ---- D regs -> per-K-group slab [128 rows][64 cols f32] ----
#pragma unroll
            for (int mt = 0; mt < 4; ++mt)
#pragma unroll
                for (int nt = 0; nt < 4; ++nt) {
                    int row0 = wm * 64 + mt * 16 + (lane >> 2);
                    int col  = wn * 32 + nt * 8 + (lane & 3) * 2;
                    u32 a0 = myslab + row0 * SLAB_STRIDE + col * 4;
                    STS64F(a0, D[mt][nt][0], D[mt][nt][1]);
                    STS64F(a0 + 8 * SLAB_STRIDE, D[mt][nt][2], D[mt][nt][3]);
                }
            asm volatile("bar.sync 1, 256;" ::: "memory");

            // ---- epilogue: 256 threads, thread owns (row = t&127, half) ----
            {
                int row  = t & 127;
                int half = t >> 7;                 // 8 hidden units each
                int b = b0 + row;
                int lt  = __ldg(letter_seq + b * S_ + s);
                int stt = __ldg(state_seq + b * S_ + s);
                const float4* pl = (const float4*)(g_projL + lt * G4 + c0 + half * 32);
                const float4* ps = (const float4*)(g_projS + stt * G4 + c0 + half * 32);
                u32 r0 = sb + SM_STAGE + row * SLAB_STRIDE + half * 128;
                u32 r1 = r0 + SLAB_HALF;
                float hv[8], cv[8];
                union { __half h[8]; int4 v; } uh;
#pragma unroll
                for (int u = 0; u < 8; ++u) {
                    float4 x0, x1;
                    LDS128F(x0, r0 + u * 16);
                    LDS128F(x1, r1 + u * 16);
                    float4 a = __ldg(pl + u);
                    float4 p = __ldg(ps + u);
                    float xi = x0.x + x1.x + a.x + p.x;
                    float xf = x0.y + x1.y + a.y + p.y;
                    float xg = x0.z + x1.z + a.z + p.z;
                    float xo = x0.w + x1.w + a.w + p.w;
                    float I = sigf(xi), F = sigf(xf), O = sigf(xo), G = tanhfast(xg);
                    float cc = F * cst[u] + I * G;
                    cst[u] = cc;
                    float hh = O * tanhfast(cc);
                    hv[u] = hh; cv[u] = cc;
                    uh.h[u] = __float2half(hh);
                }
                size_t base = (size_t)b * (S_ * H_) + (size_t)s * H_ + k0 + half * 8;
                float4* po = (float4*)(out + base);
                float4* pc = (float4*)(out + (size_t)B_ * S_ * H_ + base);
                po[0] = make_float4(hv[0], hv[1], hv[2], hv[3]);
                po[1] = make_float4(hv[4], hv[5], hv[6], hv[7]);
                pc[0] = make_float4(cv[0], cv[1], cv[2], cv[3]);
                pc[1] = make_float4(cv[4], cv[5], cv[6], cv[7]);
                int par = (s + 1) & 1;
                *(int4*)(&g_h16[par][b * H_ + k0 + half * 8]) = uh.v;
            }

            // ---- step-end: block sync + per-bt grid barrier ----
            __syncthreads();
            if (t == 0) {
                __threadfence();
                atomicAdd(&g_bars[bt * 32], 1u);
                u32 target = (u32)(s + 1) * 64u;
                while (*((volatile u32*)&g_bars[bt * 32]) < target) { }
                __threadfence();
            }
            __syncthreads();
        }
    } else {
        // ======================= PRODUCER warps (4) =======================
        const int t2 = t - 256;                      // 0..127
        u32 ephase = 1;                              // fresh-barrier trick

        for (int s = 0; s < S_; ++s) {
            const __half* hp = g_h16[s & 1];

            for (int ch = 0; ch < 16; ++ch) {
                int st = ch & 3;
                MBWAIT(sb + SM_EMPTY + 8 * st, ephase);
                if (st == 3) ephase ^= 1;
                u32 stg = sb + SM_STAGE + st * STAGE_SZ;
                int kk0 = ch * 64;
#pragma unroll
                for (int i = 0; i < 8; i++) {        // 1024 16B segs / 128 thr
                    int seg = t2 + 128 * i;
                    int r = seg >> 3, q = seg & 7;
                    CP16(stg + SWZ(r * 128 + q * 16),
                         hp + (size_t)(b0 + r) * H_ + kk0 + q * 8);
                }
                CP_COMMIT();
                if (ch >= 2) {
                    CP_WAIT2();                      // chunk ch-2 landed
                    MBARRIVE(sb + SM_FULL + 8 * ((ch - 2) & 3));
                }
            }
            CP_WAIT1();
            MBARRIVE(sb + SM_FULL + 8 * 2);          // chunk 14
            CP_WAIT0();
            MBARRIVE(sb + SM_FULL + 8 * 3);          // chunk 15

            __syncthreads();                         // step-end sync (pair 1)
            __syncthreads();                         // step-end sync (pair 2)
        }
    }
}

// ---------------------------------------------------------------------------
extern "C" void kernel_launch(void* const* d_in, const int* in_sizes, int n_in,
                              void* d_out, int out_size) {
    const int*   letter_seq = (const int*)d_in[0];
    const int*   state_seq  = (const int*)d_in[1];
    const float* letter_emb = (const float*)d_in[2];
    const float* state_emb  = (const float*)d_in[3];
    const float* W_ih       = (const float*)d_in[4];
    const float* W_hh       = (const float*)d_in[5];
    const float* b_ih       = (const float*)d_in[6];
    const float* b_hh       = (const float*)d_in[7];
    float* out = (float*)d_out;

    cudaFuncSetAttribute(lstm_kernel,
                         cudaFuncAttributeMaxDynamicSharedMemorySize, SMEM_TOTAL);

    zero_kernel<<<(B_ * H_ + 255) / 256, 256>>>();
    proj_kernel<<<(34 * G4 + 255) / 256, 256>>>(letter_emb, state_emb, W_ih, b_ih, b_hh);
    wt_kernel<<<((size_t)G4 * H_ + 255) / 256, 256>>>(W_hh);
    lstm_kernel<<<128, 384, SMEM_TOTAL>>>(letter_seq, state_seq, out);
}